// round 2
// baseline (speedup 1.0000x reference)
#include <cuda_runtime.h>
#include <math.h>

// ---------------------------------------------------------------------------
// Problem constants
// ---------------------------------------------------------------------------
#define EMB_D    512
#define HID_D    1024
#define T_LEN    512
#define B_SZ     64
#define G4       4096                  // 4*HID
#define MROWS    (T_LEN * B_SZ)        // 32768
#define LORA_SCALE 2.0f                // alpha/r = 16/8
#define NB       128                   // persistent scan grid size

// ---------------------------------------------------------------------------
// Scratch (device globals: allocation-free rule)
// ---------------------------------------------------------------------------
__device__ float g_Wih0[(size_t)G4 * EMB_D];
__device__ float g_Whh0[(size_t)G4 * HID_D];
__device__ float g_Wih1[(size_t)G4 * HID_D];
__device__ float g_Whh1[(size_t)G4 * HID_D];
__device__ float g_xp[(size_t)MROWS * G4];      // input projections [t][b][4096]
__device__ float g_hseq[(size_t)MROWS * HID_D]; // layer-0 hidden seq
__device__ float g_h[B_SZ * HID_D];
__device__ float g_c[B_SZ * HID_D];
__device__ float g_part[4 * B_SZ * G4];         // k-split partial gates
__device__ int   g_rowidx[MROWS];
__device__ unsigned int g_bar;                  // grid barrier counter

// ---------------------------------------------------------------------------
// f32x2 packed-FMA helpers (sm_100+; 2x fp32 FMA throughput vs 3-reg FFMA)
// ---------------------------------------------------------------------------
__device__ __forceinline__ void fma2(unsigned long long& acc,
                                     unsigned long long a, unsigned long long b) {
    asm("fma.rn.f32x2 %0, %1, %2, %0;" : "+l"(acc) : "l"(a), "l"(b));
}
__device__ __forceinline__ unsigned long long dup2(float x) {
    unsigned long long r;
    asm("mov.b64 %0, {%1, %1};" : "=l"(r) : "f"(x));
    return r;
}
__device__ __forceinline__ float lo32(unsigned long long v) {
    return __uint_as_float((unsigned int)v);
}
__device__ __forceinline__ float hi32(unsigned long long v) {
    return __uint_as_float((unsigned int)(v >> 32));
}

// ---------------------------------------------------------------------------
// Grid barrier (persistent kernel; monotonic counter, reset per launch)
// ---------------------------------------------------------------------------
__device__ __forceinline__ void grid_bar(unsigned int target) {
    __syncthreads();
    if (threadIdx.x == 0) {
        __threadfence();
        atomicAdd(&g_bar, 1u);
        unsigned int v;
        do {
            asm volatile("ld.global.cg.u32 %0, [%1];" : "=r"(v) : "l"(&g_bar));
            if (v >= target) break;
            __nanosleep(64);
        } while (true);
    }
    __syncthreads();
}

// ---------------------------------------------------------------------------
// Fold LoRA: W_eff = W + scale * (B @ A)
// ---------------------------------------------------------------------------
__global__ void fold_kernel(const float* __restrict__ W, const float* __restrict__ A,
                            const float* __restrict__ Bm, int D, int which)
{
    float* dst = (which == 0) ? g_Wih0 : (which == 1) ? g_Whh0
               : (which == 2) ? g_Wih1 : g_Whh1;
    int idx = blockIdx.x * blockDim.x + threadIdx.x;
    if (idx >= G4 * D) return;
    int g = idx / D;
    int d = idx - g * D;
    float s = 0.f;
#pragma unroll
    for (int r = 0; r < 8; ++r) s += Bm[g * 8 + r] * A[r * D + d];
    dst[idx] = W[idx] + LORA_SCALE * s;
}

__global__ void rowidx_kernel(const int* __restrict__ x)
{
    int m = blockIdx.x * blockDim.x + threadIdx.x;
    if (m >= MROWS) return;
    int b = m & (B_SZ - 1);
    int t = m >> 6;
    g_rowidx[m] = x[b * T_LEN + t];
}

__global__ void initstate_kernel()
{
    int idx = blockIdx.x * blockDim.x + threadIdx.x;
    if (idx < B_SZ * HID_D) { g_h[idx] = 0.f; g_c[idx] = 0.f; }
    if (idx == 0) g_bar = 0u;
}

// ---------------------------------------------------------------------------
// Input projection GEMM: g_xp[m][n] = sum_k A[m][k] * Weff[n][k] + bias[n]
// CTA 128x128, KTILE 8, 256 threads, f32x2 accumulation (M-paired).
// ---------------------------------------------------------------------------
__global__ void __launch_bounds__(256) proj_gemm(const float* __restrict__ embp,
                                                 const float* __restrict__ bias,
                                                 int mode)
{
    __shared__ float As[8][132];
    __shared__ float Bs[8][132];

    const float* W = mode ? g_Wih1 : g_Wih0;
    const int K = mode ? HID_D : EMB_D;

    int n0 = blockIdx.x * 128;
    int m0 = blockIdx.y * 128;
    int tid = threadIdx.x;

    int lr = tid >> 1;
    int lk = (tid & 1) * 4;

    const float* Arow;
    if (mode == 0) Arow = embp + (size_t)g_rowidx[m0 + lr] * EMB_D;
    else           Arow = g_hseq + (size_t)(m0 + lr) * HID_D;
    const float* Brow = W + (size_t)(n0 + lr) * K;

    int ry = (tid >> 4) * 4;   // 0..60
    int rx = (tid & 15) * 4;   // 0..60

    // acc2[i2][j]: i2 row-pairs {(ry,ry+1),(ry+2,ry+3),(ry+64,ry+65),(ry+66,ry+67)}
    //             j cols {rx..rx+3, rx+64..rx+67}
    unsigned long long acc2[4][8];
#pragma unroll
    for (int i = 0; i < 4; ++i)
#pragma unroll
        for (int j = 0; j < 8; ++j) acc2[i][j] = 0ull;

    for (int k0 = 0; k0 < K; k0 += 8) {
        float4 av = *(const float4*)(Arow + k0 + lk);
        float4 bv = *(const float4*)(Brow + k0 + lk);
        As[lk + 0][lr] = av.x; As[lk + 1][lr] = av.y;
        As[lk + 2][lr] = av.z; As[lk + 3][lr] = av.w;
        Bs[lk + 0][lr] = bv.x; Bs[lk + 1][lr] = bv.y;
        Bs[lk + 2][lr] = bv.z; Bs[lk + 3][lr] = bv.w;
        __syncthreads();
#pragma unroll
        for (int kk = 0; kk < 8; ++kk) {
            ulonglong2 aA = *(const ulonglong2*)&As[kk][ry];
            ulonglong2 aB = *(const ulonglong2*)&As[kk][ry + 64];
            float4 b0 = *(const float4*)&Bs[kk][rx];
            float4 b1 = *(const float4*)&Bs[kk][rx + 64];
            unsigned long long bd[8];
            bd[0] = dup2(b0.x); bd[1] = dup2(b0.y);
            bd[2] = dup2(b0.z); bd[3] = dup2(b0.w);
            bd[4] = dup2(b1.x); bd[5] = dup2(b1.y);
            bd[6] = dup2(b1.z); bd[7] = dup2(b1.w);
#pragma unroll
            for (int j = 0; j < 8; ++j) {
                fma2(acc2[0][j], aA.x, bd[j]);
                fma2(acc2[1][j], aA.y, bd[j]);
                fma2(acc2[2][j], aB.x, bd[j]);
                fma2(acc2[3][j], aB.y, bd[j]);
            }
        }
        __syncthreads();
    }

    // epilogue: +bias, 8 rows x 8 cols per thread
#pragma unroll
    for (int i2 = 0; i2 < 4; ++i2) {
        int rbase = (i2 < 2) ? (ry + 2 * i2) : (64 + ry + 2 * (i2 - 2));
#pragma unroll
        for (int half = 0; half < 2; ++half) {
            int m = m0 + rbase + half;
            float* Crow = g_xp + (size_t)m * G4 + n0;
            float4 o0, o1;
            float v0 = half ? hi32(acc2[i2][0]) : lo32(acc2[i2][0]);
            float v1 = half ? hi32(acc2[i2][1]) : lo32(acc2[i2][1]);
            float v2 = half ? hi32(acc2[i2][2]) : lo32(acc2[i2][2]);
            float v3 = half ? hi32(acc2[i2][3]) : lo32(acc2[i2][3]);
            float v4 = half ? hi32(acc2[i2][4]) : lo32(acc2[i2][4]);
            float v5 = half ? hi32(acc2[i2][5]) : lo32(acc2[i2][5]);
            float v6 = half ? hi32(acc2[i2][6]) : lo32(acc2[i2][6]);
            float v7 = half ? hi32(acc2[i2][7]) : lo32(acc2[i2][7]);
            o0.x = v0 + bias[n0 + rx + 0];
            o0.y = v1 + bias[n0 + rx + 1];
            o0.z = v2 + bias[n0 + rx + 2];
            o0.w = v3 + bias[n0 + rx + 3];
            o1.x = v4 + bias[n0 + rx + 64];
            o1.y = v5 + bias[n0 + rx + 65];
            o1.z = v6 + bias[n0 + rx + 66];
            o1.w = v7 + bias[n0 + rx + 67];
            *(float4*)&Crow[rx]      = o0;
            *(float4*)&Crow[rx + 64] = o1;
        }
    }
}

// ---------------------------------------------------------------------------
// Persistent scan kernel: 512 steps of (gate GEMM k-split x4 -> barrier ->
// cell -> barrier). 128 CTAs x 256 threads, all co-resident.
// ---------------------------------------------------------------------------
__global__ void __launch_bounds__(256) scan_kernel(int layer,
                                                   const float* __restrict__ bhh,
                                                   const int* __restrict__ lengths,
                                                   float* __restrict__ out)
{
    __shared__ float Hs[16][68];
    __shared__ float Ws[16][132];

    const float* W = layer ? g_Whh1 : g_Whh0;
    int nt = blockIdx.x & 31;
    int ks = blockIdx.x >> 5;
    int n0 = nt * 128;
    int kbase = ks * 256;
    int tid = threadIdx.x;

    int hb = tid >> 2;          // 0..63
    int hk = (tid & 3) * 4;     // 0,4,8,12
    int wn = tid >> 1;          // 0..127
    int wk = (tid & 1) * 8;     // 0,8

    int ry = (tid >> 5) * 4;    // 0..28
    int rx = (tid & 31) * 4;    // 0..124

    int gtid = blockIdx.x * 256 + tid;   // 0..32767 (cell phase)

    unsigned int target = 0;

    for (int t = 0; t < T_LEN; ++t) {
        // ---------------- phase A: partial gate GEMM ----------------
        // acc2[i2][j]: i2 row-pairs {(ry,ry+1),(ry+2,ry+3),(ry+32,ry+33),(ry+34,ry+35)}
        unsigned long long acc2[4][4];
#pragma unroll
        for (int i = 0; i < 4; ++i)
#pragma unroll
            for (int j = 0; j < 4; ++j) acc2[i][j] = 0ull;

        for (int k0 = 0; k0 < 256; k0 += 16) {
            float4 hv = __ldcg((const float4*)&g_h[hb * HID_D + kbase + k0 + hk]);
            Hs[hk + 0][hb] = hv.x; Hs[hk + 1][hb] = hv.y;
            Hs[hk + 2][hb] = hv.z; Hs[hk + 3][hb] = hv.w;

            const float* wrow = W + (size_t)(n0 + wn) * HID_D + kbase + k0 + wk;
            float4 w0 = *(const float4*)wrow;
            float4 w1 = *(const float4*)(wrow + 4);
            Ws[wk + 0][wn] = w0.x; Ws[wk + 1][wn] = w0.y;
            Ws[wk + 2][wn] = w0.z; Ws[wk + 3][wn] = w0.w;
            Ws[wk + 4][wn] = w1.x; Ws[wk + 5][wn] = w1.y;
            Ws[wk + 6][wn] = w1.z; Ws[wk + 7][wn] = w1.w;
            __syncthreads();
#pragma unroll
            for (int kk = 0; kk < 16; ++kk) {
                ulonglong2 a0 = *(const ulonglong2*)&Hs[kk][ry];
                ulonglong2 a1 = *(const ulonglong2*)&Hs[kk][ry + 32];
                float4 bv = *(const float4*)&Ws[kk][rx];
                unsigned long long bd0 = dup2(bv.x), bd1 = dup2(bv.y);
                unsigned long long bd2 = dup2(bv.z), bd3 = dup2(bv.w);
                fma2(acc2[0][0], a0.x, bd0); fma2(acc2[0][1], a0.x, bd1);
                fma2(acc2[0][2], a0.x, bd2); fma2(acc2[0][3], a0.x, bd3);
                fma2(acc2[1][0], a0.y, bd0); fma2(acc2[1][1], a0.y, bd1);
                fma2(acc2[1][2], a0.y, bd2); fma2(acc2[1][3], a0.y, bd3);
                fma2(acc2[2][0], a1.x, bd0); fma2(acc2[2][1], a1.x, bd1);
                fma2(acc2[2][2], a1.x, bd2); fma2(acc2[2][3], a1.x, bd3);
                fma2(acc2[3][0], a1.y, bd0); fma2(acc2[3][1], a1.y, bd1);
                fma2(acc2[3][2], a1.y, bd2); fma2(acc2[3][3], a1.y, bd3);
            }
            __syncthreads();
        }

        float* P = g_part + (size_t)ks * (B_SZ * G4);
#pragma unroll
        for (int i2 = 0; i2 < 4; ++i2) {
            int rbase = (i2 < 2) ? (ry + 2 * i2) : (32 + ry + 2 * (i2 - 2));
#pragma unroll
            for (int half = 0; half < 2; ++half) {
                int b = rbase + half;
                float4 o;
                o.x = half ? hi32(acc2[i2][0]) : lo32(acc2[i2][0]);
                o.y = half ? hi32(acc2[i2][1]) : lo32(acc2[i2][1]);
                o.z = half ? hi32(acc2[i2][2]) : lo32(acc2[i2][2]);
                o.w = half ? hi32(acc2[i2][3]) : lo32(acc2[i2][3]);
                __stcg((float4*)&P[(size_t)b * G4 + n0 + rx], o);
            }
        }

        target += NB;
        grid_bar(target);

        // ---------------- phase B: reduce + LSTM cell ----------------
#pragma unroll
        for (int e = 0; e < 2; ++e) {
            int idx = gtid + e * 32768;          // 0..65535
            int b = idx >> 10;
            int j = idx & 1023;

            const float* xp = g_xp + ((size_t)t * B_SZ + b) * G4 + j;
            float gi = __ldcg(xp)        + bhh[j];
            float gf = __ldcg(xp + 1024) + bhh[1024 + j];
            float gg = __ldcg(xp + 2048) + bhh[2048 + j];
            float go = __ldcg(xp + 3072) + bhh[3072 + j];
#pragma unroll
            for (int s = 0; s < 4; ++s) {
                const float* p = g_part + ((size_t)s * B_SZ + b) * G4 + j;
                gi += __ldcg(p);
                gf += __ldcg(p + 1024);
                gg += __ldcg(p + 2048);
                go += __ldcg(p + 3072);
            }

            float c = __ldcg(&g_c[idx]);
            float si = 1.f / (1.f + expf(-gi));
            float sf = 1.f / (1.f + expf(-gf));
            float so = 1.f / (1.f + expf(-go));
            float cg = tanhf(gg);
            c = sf * c + si * cg;
            float h = so * tanhf(c);

            __stcg(&g_c[idx], c);
            __stcg(&g_h[idx], h);

            if (layer == 0) {
                __stcg(&g_hseq[((size_t)t * B_SZ + b) * HID_D + j], h);
            } else {
                int L = lengths[b] - 1;
                if (L < 0) L = 0;
                if (t == L) out[(size_t)b * HID_D + j] = h;
            }
        }

        target += NB;
        grid_bar(target);
    }
}

// ---------------------------------------------------------------------------
// Launcher (10 graph nodes total)
// ---------------------------------------------------------------------------
extern "C" void kernel_launch(void* const* d_in, const int* in_sizes, int n_in,
                              void* d_out, int out_size)
{
    const int*   x    = (const int*)d_in[0];
    const int*   len  = (const int*)d_in[1];
    const float* emb  = (const float*)d_in[2];
    const float* Wih0 = (const float*)d_in[3];
    const float* bih0 = (const float*)d_in[4];
    const float* Aih0 = (const float*)d_in[5];
    const float* Bih0 = (const float*)d_in[6];
    const float* Whh0 = (const float*)d_in[7];
    const float* bhh0 = (const float*)d_in[8];
    const float* Ahh0 = (const float*)d_in[9];
    const float* Bhh0 = (const float*)d_in[10];
    const float* Wih1 = (const float*)d_in[11];
    const float* bih1 = (const float*)d_in[12];
    const float* Aih1 = (const float*)d_in[13];
    const float* Bih1 = (const float*)d_in[14];
    const float* Whh1 = (const float*)d_in[15];
    const float* bhh1 = (const float*)d_in[16];
    const float* Ahh1 = (const float*)d_in[17];
    const float* Bhh1 = (const float*)d_in[18];
    float* out = (float*)d_out;

    int n0 = G4 * EMB_D, n1 = G4 * HID_D;
    fold_kernel<<<(n0 + 255) / 256, 256>>>(Wih0, Aih0, Bih0, EMB_D, 0);
    fold_kernel<<<(n1 + 255) / 256, 256>>>(Whh0, Ahh0, Bhh0, HID_D, 1);
    fold_kernel<<<(n1 + 255) / 256, 256>>>(Wih1, Aih1, Bih1, HID_D, 2);
    fold_kernel<<<(n1 + 255) / 256, 256>>>(Whh1, Ahh1, Bhh1, HID_D, 3);

    rowidx_kernel<<<(MROWS + 255) / 256, 256>>>(x);

    dim3 pgrid(G4 / 128, MROWS / 128);
    int cellBlocks = (B_SZ * HID_D + 255) / 256;

    // layer 0
    proj_gemm<<<pgrid, 256>>>(emb, bih0, 0);
    initstate_kernel<<<cellBlocks, 256>>>();
    scan_kernel<<<NB, 256>>>(0, bhh0, len, out);

    // layer 1
    proj_gemm<<<pgrid, 256>>>(nullptr, bih1, 1);
    initstate_kernel<<<cellBlocks, 256>>>();
    scan_kernel<<<NB, 256>>>(1, bhh1, len, out);
}

// round 4
// speedup vs baseline: 1.6684x; 1.6684x over previous
#include <cuda_runtime.h>
#include <math.h>
#include <stdint.h>

// ---------------------------------------------------------------------------
// Problem constants
// ---------------------------------------------------------------------------
#define EMB_D    512
#define HID_D    1024
#define T_LEN    512
#define B_SZ     64
#define G4       4096                  // 4*HID
#define MROWS    (T_LEN * B_SZ)        // 32768
#define LORA_SCALE 2.0f                // alpha/r = 16/8
#define NB       128                   // persistent scan grid size

// ---------------------------------------------------------------------------
// Scratch (device globals: allocation-free rule)
// ---------------------------------------------------------------------------
__device__ float g_Wih0[(size_t)G4 * EMB_D];    // folded W_ih0 (row-major)
__device__ float g_Wih1[(size_t)G4 * HID_D];    // folded W_ih1 (row-major)
__device__ float g_Wp0[(size_t)G4 * HID_D];     // folded W_hh0, fragment-packed tf32
__device__ float g_Wp1[(size_t)G4 * HID_D];     // folded W_hh1, fragment-packed tf32
__device__ float g_xp[(size_t)MROWS * G4];      // input projections [t][b][4096]
__device__ float g_hseq[(size_t)MROWS * HID_D]; // layer-0 hidden seq
__device__ float g_h[B_SZ * HID_D];
__device__ float g_c[B_SZ * HID_D];
__device__ float g_part[4 * B_SZ * G4];         // k-split partial gates
__device__ int   g_rowidx[MROWS];
__device__ unsigned int g_bar;                  // grid barrier counter

// ---------------------------------------------------------------------------
// tf32 helpers (portable PTX: works on compute_103 virtual arch)
// ---------------------------------------------------------------------------
__device__ __forceinline__ float to_tf32(float x) {
    float r;
    asm("cvt.rna.tf32.f32 %0, %1;" : "=f"(r) : "f"(x));
    return r;
}
#define CVT4(v) do { (v).x = to_tf32((v).x); (v).y = to_tf32((v).y); \
                     (v).z = to_tf32((v).z); (v).w = to_tf32((v).w); } while (0)

// D += A(16x8,row) * B(8x8,col); tf32 inputs (as f32 bit patterns), f32 accum
__device__ __forceinline__ void mma8(float4& c, const float a0, const float a1,
                                     const float a2, const float a3,
                                     uint32_t b0, uint32_t b1) {
    asm volatile(
        "mma.sync.aligned.m16n8k8.row.col.f32.tf32.tf32.f32 "
        "{%0,%1,%2,%3}, {%4,%5,%6,%7}, {%8,%9}, {%0,%1,%2,%3};"
        : "+f"(c.x), "+f"(c.y), "+f"(c.z), "+f"(c.w)
        : "r"(__float_as_uint(a0)), "r"(__float_as_uint(a1)),
          "r"(__float_as_uint(a2)), "r"(__float_as_uint(a3)),
          "r"(b0), "r"(b1));
}

// ---------------------------------------------------------------------------
// Grid barrier (persistent scan)
// ---------------------------------------------------------------------------
__device__ __forceinline__ void grid_bar(unsigned int target) {
    __syncthreads();
    if (threadIdx.x == 0) {
        __threadfence();
        atomicAdd(&g_bar, 1u);
        unsigned int v;
        do {
            asm volatile("ld.global.cg.u32 %0, [%1];" : "=r"(v) : "l"(&g_bar));
            if (v >= target) break;
            __nanosleep(64);
        } while (true);
    }
    __syncthreads();
}

// ---------------------------------------------------------------------------
// Fold LoRA for input-projection weights (row-major fp32; cvt at staging)
// ---------------------------------------------------------------------------
__global__ void fold_kernel(const float* __restrict__ W, const float* __restrict__ A,
                            const float* __restrict__ Bm, int D, int which)
{
    float* dst = which ? g_Wih1 : g_Wih0;
    int idx = blockIdx.x * blockDim.x + threadIdx.x;
    if (idx >= G4 * D) return;
    int g = idx / D;
    int d = idx - g * D;
    float s = 0.f;
#pragma unroll
    for (int r = 0; r < 8; ++r) s += Bm[g * 8 + r] * A[r * D + d];
    dst[idx] = W[idx] + LORA_SCALE * s;
}

// ---------------------------------------------------------------------------
// Fold + fragment-pack W_hh into tf32, layout:
//   [nt(32)][ksl(4)][wn(4)][ks(32)][j(4)][lane(32)][r(2)]
// element: n = nt*128 + wn*32 + j*8 + (lane>>2)
//          k = ksl*256 + ks*8 + (lane&3) + r*4
// ---------------------------------------------------------------------------
__global__ void pack_fold(const float* __restrict__ W, const float* __restrict__ A,
                          const float* __restrict__ Bm, int layer)
{
    int p = blockIdx.x * 256 + threadIdx.x;
    if (p >= G4 * HID_D) return;
    int r   = p & 1;
    int l   = (p >> 1) & 31;
    int j   = (p >> 6) & 3;
    int ks  = (p >> 8) & 31;
    int wn  = (p >> 13) & 3;
    int ksl = (p >> 15) & 3;
    int nt  = p >> 17;
    int n = nt * 128 + wn * 32 + j * 8 + (l >> 2);
    int k = ksl * 256 + ks * 8 + (l & 3) + r * 4;
    float s = 0.f;
#pragma unroll
    for (int rr = 0; rr < 8; ++rr) s += Bm[n * 8 + rr] * A[rr * HID_D + k];
    float v = W[(size_t)n * HID_D + k] + LORA_SCALE * s;
    (layer ? g_Wp1 : g_Wp0)[p] = to_tf32(v);
}

__global__ void rowidx_kernel(const int* __restrict__ x)
{
    int m = blockIdx.x * blockDim.x + threadIdx.x;
    if (m >= MROWS) return;
    int b = m & (B_SZ - 1);
    int t = m >> 6;
    g_rowidx[m] = x[b * T_LEN + t];
}

__global__ void initstate_kernel()
{
    int idx = blockIdx.x * blockDim.x + threadIdx.x;
    if (idx < B_SZ * HID_D) { g_h[idx] = 0.f; g_c[idx] = 0.f; }
    if (idx == 0) g_bar = 0u;
}

// ---------------------------------------------------------------------------
// Input projection GEMM via mma.sync tf32:
//   g_xp[m][n] = sum_k A[m][k] * Weff[n][k] + bias[n]
// CTA 128(M)x128(N), K staged in 32-chunks. 8 warps: warp tile 32m x 64n.
// mode 0: A = emb[rowidx[m]], K=512 ; mode 1: A = g_hseq[m], K=1024
// ---------------------------------------------------------------------------
__global__ void __launch_bounds__(256) proj_gemm(const float* __restrict__ embp,
                                                 const float* __restrict__ bias,
                                                 int mode)
{
    __shared__ float As[128 * 36];   // stride 36: conflict-free frag reads
    __shared__ float Bs[128 * 36];

    const float* W = mode ? g_Wih1 : g_Wih0;
    const int K = mode ? HID_D : EMB_D;

    int n0 = blockIdx.x * 128;
    int m0 = blockIdx.y * 128;
    int tid = threadIdx.x;
    int w = tid >> 5, lid = tid & 31;
    int g = lid >> 2, t4 = lid & 3;
    int wm = w >> 1, wn = w & 1;          // 4 x 2 warp grid
    int m0w = wm * 32, n0w = wn * 64;

    // staging map: thread covers row (tid>>1), k-half 16 floats
    int srow = tid >> 1;
    int sh16 = (tid & 1) * 16;
    const float* arow0;
    if (mode == 0) arow0 = embp + (size_t)g_rowidx[m0 + srow] * EMB_D;
    else           arow0 = g_hseq + (size_t)(m0 + srow) * HID_D;
    const float* brow0 = W + (size_t)(n0 + srow) * K;

    float4 c[2][8];
#pragma unroll
    for (int i = 0; i < 2; ++i)
#pragma unroll
        for (int j = 0; j < 8; ++j) c[i][j] = make_float4(0.f, 0.f, 0.f, 0.f);

    for (int k0 = 0; k0 < K; k0 += 32) {
        // stage A,B (with tf32 convert)
#pragma unroll
        for (int j = 0; j < 4; ++j) {
            float4 va = *(const float4*)(arow0 + k0 + sh16 + j * 4);
            CVT4(va);
            *(float4*)&As[srow * 36 + sh16 + j * 4] = va;
            float4 vb = *(const float4*)(brow0 + k0 + sh16 + j * 4);
            CVT4(vb);
            *(float4*)&Bs[srow * 36 + sh16 + j * 4] = vb;
        }
        __syncthreads();

#pragma unroll
        for (int ks = 0; ks < 4; ++ks) {
            int kk = ks * 8;
            float a[2][4];
#pragma unroll
            for (int mt = 0; mt < 2; ++mt) {
                const float* ab = &As[(m0w + mt * 16 + g) * 36 + kk + t4];
                a[mt][0] = ab[0];
                a[mt][2] = ab[4];
                a[mt][1] = ab[8 * 36];
                a[mt][3] = ab[8 * 36 + 4];
            }
#pragma unroll
            for (int j = 0; j < 8; ++j) {
                const float* bb = &Bs[(n0w + j * 8 + g) * 36 + kk + t4];
                uint32_t b0 = __float_as_uint(bb[0]);
                uint32_t b1 = __float_as_uint(bb[4]);
#pragma unroll
                for (int mt = 0; mt < 2; ++mt)
                    mma8(c[mt][j], a[mt][0], a[mt][1], a[mt][2], a[mt][3], b0, b1);
            }
        }
        __syncthreads();
    }

    // epilogue: +bias, write fp32
#pragma unroll
    for (int mt = 0; mt < 2; ++mt) {
#pragma unroll
        for (int j = 0; j < 8; ++j) {
            int row0 = m0 + m0w + mt * 16 + g;
            int col  = n0 + n0w + j * 8 + 2 * t4;
            float b0 = bias[col], b1 = bias[col + 1];
            float2 o0 = make_float2(c[mt][j].x + b0, c[mt][j].y + b1);
            float2 o1 = make_float2(c[mt][j].z + b0, c[mt][j].w + b1);
            *(float2*)&g_xp[(size_t)row0 * G4 + col] = o0;
            *(float2*)&g_xp[(size_t)(row0 + 8) * G4 + col] = o1;
        }
    }
}

// ---------------------------------------------------------------------------
// Persistent scan kernel: 512 steps of (tf32 mma gate GEMM (k-split x4)
// -> barrier -> cell -> barrier). 128 CTAs x 256 threads.
// CTA: 64m x 128n x 256k. Warps: 2(wm) x 4(wn), warp tile 32m x 32n.
// ---------------------------------------------------------------------------
__global__ void __launch_bounds__(256) scan_kernel(int layer,
                                                   const float* __restrict__ bhh,
                                                   const int* __restrict__ lengths,
                                                   float* __restrict__ out)
{
    __shared__ float Hs[64 * 132];   // 33 KB: 64 rows x 128 k (stride 132)

    int nt = blockIdx.x & 31;
    int ksl = blockIdx.x >> 5;
    int n0 = nt * 128;
    int kbase = ksl * 256;
    int tid = threadIdx.x;
    int w = tid >> 5, lid = tid & 31;
    int g = lid >> 2, t4 = lid & 3;
    int wm = w >> 2, wn = w & 3;
    int m0w = wm * 32, n0w = wn * 32;

    const float* Wp = (layer ? g_Wp1 : g_Wp0)
                    + (size_t)(((nt * 4 + ksl) * 4 + wn)) * 8192;

    // staging map: thread -> row (tid>>2), 32-float k-chunk (tid&3)
    int srow = tid >> 2;
    int sq = (tid & 3) * 32;

    int gtid = blockIdx.x * 256 + tid;
    unsigned int target = 0;

    for (int t = 0; t < T_LEN; ++t) {
        float4 c[2][4];
#pragma unroll
        for (int i = 0; i < 2; ++i)
#pragma unroll
            for (int j = 0; j < 4; ++j) c[i][j] = make_float4(0.f, 0.f, 0.f, 0.f);

#pragma unroll
        for (int half = 0; half < 2; ++half) {
            // stage h k-half [kbase+half*128, +128) with tf32 convert
            const float* hp = &g_h[srow * HID_D + kbase + half * 128 + sq];
            float* hs = &Hs[srow * 132 + sq];
#pragma unroll
            for (int j = 0; j < 8; ++j) {
                float4 v = __ldcg((const float4*)(hp + j * 4));
                CVT4(v);
                *(float4*)(hs + j * 4) = v;
            }
            __syncthreads();

            const float* WpH = Wp + half * (16 * 4 * 64);
#pragma unroll
            for (int ks = 0; ks < 16; ++ks) {
                int kk = ks * 8;
                float a[2][4];
#pragma unroll
                for (int mt = 0; mt < 2; ++mt) {
                    const float* ab = &Hs[(m0w + mt * 16 + g) * 132 + kk + t4];
                    a[mt][0] = ab[0];
                    a[mt][2] = ab[4];
                    a[mt][1] = ab[8 * 132];
                    a[mt][3] = ab[8 * 132 + 4];
                }
#pragma unroll
                for (int j = 0; j < 4; ++j) {
                    uint2 bv = *(const uint2*)(WpH + (ks * 4 + j) * 64 + lid * 2);
#pragma unroll
                    for (int mt = 0; mt < 2; ++mt)
                        mma8(c[mt][j], a[mt][0], a[mt][1], a[mt][2], a[mt][3],
                             bv.x, bv.y);
                }
            }
            __syncthreads();
        }

        // write partial gates (.cg, L2-coherent)
        float* P = g_part + (size_t)ksl * (B_SZ * G4);
#pragma unroll
        for (int mt = 0; mt < 2; ++mt) {
#pragma unroll
            for (int j = 0; j < 4; ++j) {
                int row0 = m0w + mt * 16 + g;
                int col  = n0 + n0w + j * 8 + 2 * t4;
                __stcg((float2*)&P[(size_t)row0 * G4 + col],
                       make_float2(c[mt][j].x, c[mt][j].y));
                __stcg((float2*)&P[(size_t)(row0 + 8) * G4 + col],
                       make_float2(c[mt][j].z, c[mt][j].w));
            }
        }

        target += NB;
        grid_bar(target);

        // ---------------- cell phase ----------------
#pragma unroll
        for (int e = 0; e < 2; ++e) {
            int idx = gtid + e * 32768;
            int b = idx >> 10;
            int j = idx & 1023;

            const float* xp = g_xp + ((size_t)t * B_SZ + b) * G4 + j;
            float gi = __ldcg(xp)        + bhh[j];
            float gf = __ldcg(xp + 1024) + bhh[1024 + j];
            float gg = __ldcg(xp + 2048) + bhh[2048 + j];
            float go = __ldcg(xp + 3072) + bhh[3072 + j];
#pragma unroll
            for (int s = 0; s < 4; ++s) {
                const float* p = g_part + ((size_t)s * B_SZ + b) * G4 + j;
                gi += __ldcg(p);
                gf += __ldcg(p + 1024);
                gg += __ldcg(p + 2048);
                go += __ldcg(p + 3072);
            }

            float cc = __ldcg(&g_c[idx]);
            float si = 1.f / (1.f + expf(-gi));
            float sf = 1.f / (1.f + expf(-gf));
            float so = 1.f / (1.f + expf(-go));
            float cg = tanhf(gg);
            cc = sf * cc + si * cg;
            float h = so * tanhf(cc);

            __stcg(&g_c[idx], cc);
            __stcg(&g_h[idx], h);

            if (layer == 0) {
                __stcg(&g_hseq[((size_t)t * B_SZ + b) * HID_D + j], h);
            } else {
                int L = lengths[b] - 1;
                if (L < 0) L = 0;
                if (t == L) out[(size_t)b * HID_D + j] = h;
            }
        }

        target += NB;
        grid_bar(target);
    }
}

// ---------------------------------------------------------------------------
// Launcher (11 graph nodes)
// ---------------------------------------------------------------------------
extern "C" void kernel_launch(void* const* d_in, const int* in_sizes, int n_in,
                              void* d_out, int out_size)
{
    const int*   x    = (const int*)d_in[0];
    const int*   len  = (const int*)d_in[1];
    const float* emb  = (const float*)d_in[2];
    const float* Wih0 = (const float*)d_in[3];
    const float* bih0 = (const float*)d_in[4];
    const float* Aih0 = (const float*)d_in[5];
    const float* Bih0 = (const float*)d_in[6];
    const float* Whh0 = (const float*)d_in[7];
    const float* bhh0 = (const float*)d_in[8];
    const float* Ahh0 = (const float*)d_in[9];
    const float* Bhh0 = (const float*)d_in[10];
    const float* Wih1 = (const float*)d_in[11];
    const float* bih1 = (const float*)d_in[12];
    const float* Aih1 = (const float*)d_in[13];
    const float* Bih1 = (const float*)d_in[14];
    const float* Whh1 = (const float*)d_in[15];
    const float* bhh1 = (const float*)d_in[16];
    const float* Ahh1 = (const float*)d_in[17];
    const float* Bhh1 = (const float*)d_in[18];
    float* out = (float*)d_out;

    int n0 = G4 * EMB_D, n1 = G4 * HID_D;
    fold_kernel<<<(n0 + 255) / 256, 256>>>(Wih0, Aih0, Bih0, EMB_D, 0);
    fold_kernel<<<(n1 + 255) / 256, 256>>>(Wih1, Aih1, Bih1, HID_D, 1);
    pack_fold<<<(n1 + 255) / 256, 256>>>(Whh0, Ahh0, Bhh0, 0);
    pack_fold<<<(n1 + 255) / 256, 256>>>(Whh1, Ahh1, Bhh1, 1);

    rowidx_kernel<<<(MROWS + 255) / 256, 256>>>(x);

    dim3 pgrid(G4 / 128, MROWS / 128);   // (32 n-tiles, 256 m-tiles)
    int cellBlocks = (B_SZ * HID_D + 255) / 256;

    // layer 0
    proj_gemm<<<pgrid, 256>>>(emb, bih0, 0);
    initstate_kernel<<<cellBlocks, 256>>>();
    scan_kernel<<<NB, 256>>>(0, bhh0, len, out);

    // layer 1
    proj_gemm<<<pgrid, 256>>>(nullptr, bih1, 1);
    initstate_kernel<<<cellBlocks, 256>>>();
    scan_kernel<<<NB, 256>>>(1, bhh1, len, out);
}

// round 5
// speedup vs baseline: 1.9150x; 1.1478x over previous
#include <cuda_runtime.h>
#include <math.h>
#include <stdint.h>

// ---------------------------------------------------------------------------
// Problem constants
// ---------------------------------------------------------------------------
#define EMB_D    512
#define HID_D    1024
#define T_LEN    512
#define B_SZ     64
#define G4       4096                  // 4*HID
#define MROWS    (T_LEN * B_SZ)        // 32768
#define LORA_SCALE 2.0f                // alpha/r = 16/8
#define NB       128                   // persistent scan grid size

// ---------------------------------------------------------------------------
// Scratch (device globals: allocation-free rule)
// ---------------------------------------------------------------------------
__device__ float g_Wih0[(size_t)G4 * EMB_D];    // folded W_ih0 (row-major)
__device__ float g_Wih1[(size_t)G4 * HID_D];    // folded W_ih1 (row-major)
__device__ float g_Wp0[(size_t)G4 * HID_D];     // folded W_hh0, fragment-packed tf32
__device__ float g_Wp1[(size_t)G4 * HID_D];     // folded W_hh1, fragment-packed tf32
__device__ float g_xp[(size_t)MROWS * G4];      // input projections [t][b][4096]
__device__ float g_hseq[(size_t)MROWS * HID_D]; // layer-0 hidden seq
__device__ float g_h[B_SZ * HID_D];
__device__ float g_part[4 * B_SZ * G4];         // k-split partial gates
__device__ int   g_rowidx[MROWS];
__device__ unsigned int g_bar;                  // grid barrier counter

// ---------------------------------------------------------------------------
// tf32 helpers (portable PTX: works on compute_103 virtual arch)
// ---------------------------------------------------------------------------
__device__ __forceinline__ float to_tf32(float x) {
    float r;
    asm("cvt.rna.tf32.f32 %0, %1;" : "=f"(r) : "f"(x));
    return r;
}
#define CVT4(v) do { (v).x = to_tf32((v).x); (v).y = to_tf32((v).y); \
                     (v).z = to_tf32((v).z); (v).w = to_tf32((v).w); } while (0)

// D += A(16x8,row) * B(8x8,col); tf32 inputs (as f32 bit patterns), f32 accum
__device__ __forceinline__ void mma8(float4& c, const float a0, const float a1,
                                     const float a2, const float a3,
                                     uint32_t b0, uint32_t b1) {
    asm volatile(
        "mma.sync.aligned.m16n8k8.row.col.f32.tf32.tf32.f32 "
        "{%0,%1,%2,%3}, {%4,%5,%6,%7}, {%8,%9}, {%0,%1,%2,%3};"
        : "+f"(c.x), "+f"(c.y), "+f"(c.z), "+f"(c.w)
        : "r"(__float_as_uint(a0)), "r"(__float_as_uint(a1)),
          "r"(__float_as_uint(a2)), "r"(__float_as_uint(a3)),
          "r"(b0), "r"(b1));
}

// ---------------------------------------------------------------------------
// Grid barrier: REDG (no-return) arrival + acquire-poll release.
// Single-address returning atomics serialize at ~32cyc/op (128 CTAs ~ 4096cyc);
// REDG runs ~0.854 cyc/op. release/acquire folds in the memory ordering.
// ---------------------------------------------------------------------------
__device__ __forceinline__ void grid_bar(unsigned int target) {
    __syncthreads();
    if (threadIdx.x == 0) {
        asm volatile("red.release.gpu.global.add.u32 [%0], %1;"
                     :: "l"(&g_bar), "r"(1u) : "memory");
        unsigned int v;
        do {
            asm volatile("ld.acquire.gpu.global.u32 %0, [%1];"
                         : "=r"(v) : "l"(&g_bar) : "memory");
        } while (v < target);
    }
    __syncthreads();
}

// ---------------------------------------------------------------------------
// Fold LoRA for input-projection weights (row-major fp32; cvt at staging)
// ---------------------------------------------------------------------------
__global__ void fold_kernel(const float* __restrict__ W, const float* __restrict__ A,
                            const float* __restrict__ Bm, int D, int which)
{
    float* dst = which ? g_Wih1 : g_Wih0;
    int idx = blockIdx.x * blockDim.x + threadIdx.x;
    if (idx >= G4 * D) return;
    int g = idx / D;
    int d = idx - g * D;
    float s = 0.f;
#pragma unroll
    for (int r = 0; r < 8; ++r) s += Bm[g * 8 + r] * A[r * D + d];
    dst[idx] = W[idx] + LORA_SCALE * s;
}

// ---------------------------------------------------------------------------
// Fold + fragment-pack W_hh into tf32, layout:
//   [nt(32)][ksl(4)][wn(4)][ks(32)][j(4)][lane(32)][r(2)]
// element: n = nt*128 + wn*32 + j*8 + (lane>>2)
//          k = ksl*256 + ks*8 + (lane&3) + r*4
// ---------------------------------------------------------------------------
__global__ void pack_fold(const float* __restrict__ W, const float* __restrict__ A,
                          const float* __restrict__ Bm, int layer)
{
    int p = blockIdx.x * 256 + threadIdx.x;
    if (p >= G4 * HID_D) return;
    int r   = p & 1;
    int l   = (p >> 1) & 31;
    int j   = (p >> 6) & 3;
    int ks  = (p >> 8) & 31;
    int wn  = (p >> 13) & 3;
    int ksl = (p >> 15) & 3;
    int nt  = p >> 17;
    int n = nt * 128 + wn * 32 + j * 8 + (l >> 2);
    int k = ksl * 256 + ks * 8 + (l & 3) + r * 4;
    float s = 0.f;
#pragma unroll
    for (int rr = 0; rr < 8; ++rr) s += Bm[n * 8 + rr] * A[rr * HID_D + k];
    float v = W[(size_t)n * HID_D + k] + LORA_SCALE * s;
    (layer ? g_Wp1 : g_Wp0)[p] = to_tf32(v);
}

__global__ void rowidx_kernel(const int* __restrict__ x)
{
    int m = blockIdx.x * blockDim.x + threadIdx.x;
    if (m >= MROWS) return;
    int b = m & (B_SZ - 1);
    int t = m >> 6;
    g_rowidx[m] = x[b * T_LEN + t];
}

__global__ void initstate_kernel()
{
    int idx = blockIdx.x * blockDim.x + threadIdx.x;
    if (idx < B_SZ * HID_D) g_h[idx] = 0.f;
    if (idx == 0) g_bar = 0u;
}

// ---------------------------------------------------------------------------
// Input projection GEMM via mma.sync tf32 (early-LDG double-buffered):
//   g_xp[m][n] = sum_k A[m][k] * Weff[n][k] + bias[n]
// CTA 128(M)x128(N), K staged in 32-chunks. 8 warps: warp tile 32m x 64n.
// mode 0: A = emb[rowidx[m]], K=512 ; mode 1: A = g_hseq[m], K=1024
// ---------------------------------------------------------------------------
__global__ void __launch_bounds__(256) proj_gemm(const float* __restrict__ embp,
                                                 const float* __restrict__ bias,
                                                 int mode)
{
    __shared__ float As[128 * 36];   // stride 36: conflict-free frag reads
    __shared__ float Bs[128 * 36];

    const float* W = mode ? g_Wih1 : g_Wih0;
    const int K = mode ? HID_D : EMB_D;

    int n0 = blockIdx.x * 128;
    int m0 = blockIdx.y * 128;
    int tid = threadIdx.x;
    int w = tid >> 5, lid = tid & 31;
    int g = lid >> 2, t4 = lid & 3;
    int wm = w >> 1, wn = w & 1;          // 4 x 2 warp grid
    int m0w = wm * 32, n0w = wn * 64;

    // staging map: thread covers row (tid>>1), k-half 16 floats
    int srow = tid >> 1;
    int sh16 = (tid & 1) * 16;
    const float* arow0;
    if (mode == 0) arow0 = embp + (size_t)g_rowidx[m0 + srow] * EMB_D;
    else           arow0 = g_hseq + (size_t)(m0 + srow) * HID_D;
    const float* brow0 = W + (size_t)(n0 + srow) * K;

    float4 c[2][8];
#pragma unroll
    for (int i = 0; i < 2; ++i)
#pragma unroll
        for (int j = 0; j < 8; ++j) c[i][j] = make_float4(0.f, 0.f, 0.f, 0.f);

    // prologue: load chunk 0 into regs
    float4 va[4], vb[4];
#pragma unroll
    for (int j = 0; j < 4; ++j) {
        va[j] = *(const float4*)(arow0 + sh16 + j * 4);
        vb[j] = *(const float4*)(brow0 + sh16 + j * 4);
    }

    for (int k0 = 0; k0 < K; k0 += 32) {
        // store staged chunk (with tf32 convert)
#pragma unroll
        for (int j = 0; j < 4; ++j) {
            CVT4(va[j]);
            *(float4*)&As[srow * 36 + sh16 + j * 4] = va[j];
            CVT4(vb[j]);
            *(float4*)&Bs[srow * 36 + sh16 + j * 4] = vb[j];
        }
        __syncthreads();

        // issue next chunk's LDGs early (hidden under MMAs)
        if (k0 + 32 < K) {
#pragma unroll
            for (int j = 0; j < 4; ++j) {
                va[j] = *(const float4*)(arow0 + k0 + 32 + sh16 + j * 4);
                vb[j] = *(const float4*)(brow0 + k0 + 32 + sh16 + j * 4);
            }
        }

#pragma unroll
        for (int ks = 0; ks < 4; ++ks) {
            int kk = ks * 8;
            float a[2][4];
#pragma unroll
            for (int mt = 0; mt < 2; ++mt) {
                const float* ab = &As[(m0w + mt * 16 + g) * 36 + kk + t4];
                a[mt][0] = ab[0];
                a[mt][2] = ab[4];
                a[mt][1] = ab[8 * 36];
                a[mt][3] = ab[8 * 36 + 4];
            }
#pragma unroll
            for (int j = 0; j < 8; ++j) {
                const float* bb = &Bs[(n0w + j * 8 + g) * 36 + kk + t4];
                uint32_t b0 = __float_as_uint(bb[0]);
                uint32_t b1 = __float_as_uint(bb[4]);
#pragma unroll
                for (int mt = 0; mt < 2; ++mt)
                    mma8(c[mt][j], a[mt][0], a[mt][1], a[mt][2], a[mt][3], b0, b1);
            }
        }
        __syncthreads();
    }

    // epilogue: +bias, write fp32
#pragma unroll
    for (int mt = 0; mt < 2; ++mt) {
#pragma unroll
        for (int j = 0; j < 8; ++j) {
            int row0 = m0 + m0w + mt * 16 + g;
            int col  = n0 + n0w + j * 8 + 2 * t4;
            float b0 = bias[col], b1 = bias[col + 1];
            float2 o0 = make_float2(c[mt][j].x + b0, c[mt][j].y + b1);
            float2 o1 = make_float2(c[mt][j].z + b0, c[mt][j].w + b1);
            *(float2*)&g_xp[(size_t)row0 * G4 + col] = o0;
            *(float2*)&g_xp[(size_t)(row0 + 8) * G4 + col] = o1;
        }
    }
}

// ---------------------------------------------------------------------------
// Persistent scan kernel: 512 steps of (tf32 mma gate GEMM (k-split x4)
// -> barrier -> cell -> barrier). 128 CTAs x 256 threads.
// CTA: 64m x 128n x 256k. Warps: 2(wm) x 4(wn), warp tile 32m x 32n.
// Cell state c lives in registers (thread->element map is step-invariant).
// ---------------------------------------------------------------------------
__global__ void __launch_bounds__(256) scan_kernel(int layer,
                                                   const float* __restrict__ bhh,
                                                   const int* __restrict__ lengths,
                                                   float* __restrict__ out)
{
    __shared__ float Hs[64 * 132];   // 33 KB: 64 rows x 128 k (stride 132)

    int nt = blockIdx.x & 31;
    int ksl = blockIdx.x >> 5;
    int n0 = nt * 128;
    int kbase = ksl * 256;
    int tid = threadIdx.x;
    int w = tid >> 5, lid = tid & 31;
    int g = lid >> 2, t4 = lid & 3;
    int wm = w >> 2, wn = w & 3;
    int m0w = wm * 32, n0w = wn * 32;

    const float* Wp = (layer ? g_Wp1 : g_Wp0)
                    + (size_t)(((nt * 4 + ksl) * 4 + wn)) * 8192;

    // staging map: thread -> row (tid>>2), 32-float k-chunk (tid&3)
    int srow = tid >> 2;
    int sq = (tid & 3) * 32;

    // ---- cell-phase ownership (step-invariant): elements (b0,j0),(b0+32,j0)
    int gtid = blockIdx.x * 256 + tid;
    int b0 = gtid >> 10;
    int j0 = gtid & 1023;
    float bi = bhh[j0],        bf = bhh[1024 + j0];
    float bg = bhh[2048 + j0], bo = bhh[3072 + j0];
    int L0 = lengths[b0] - 1;      if (L0 < 0) L0 = 0;
    int L1 = lengths[b0 + 32] - 1; if (L1 < 0) L1 = 0;
    float c0 = 0.f, c1 = 0.f;

    const size_t xpstep = (size_t)B_SZ * G4;
    const float* xp0 = g_xp + (size_t)b0 * G4 + j0;          // row b0, step 0
    const float* xp1 = xp0 + (size_t)32 * G4;                // row b0+32

    unsigned int target = 0;

    for (int t = 0; t < T_LEN; ++t) {
        // prefetch this step's xp gate inputs (DRAM latency hides under GEMM)
        float x0i = __ldcg(xp0),        x0f = __ldcg(xp0 + 1024);
        float x0g = __ldcg(xp0 + 2048), x0o = __ldcg(xp0 + 3072);
        float x1i = __ldcg(xp1),        x1f = __ldcg(xp1 + 1024);
        float x1g = __ldcg(xp1 + 2048), x1o = __ldcg(xp1 + 3072);

        float4 c[2][4];
#pragma unroll
        for (int i = 0; i < 2; ++i)
#pragma unroll
            for (int j = 0; j < 4; ++j) c[i][j] = make_float4(0.f, 0.f, 0.f, 0.f);

#pragma unroll
        for (int half = 0; half < 2; ++half) {
            // stage h k-half [kbase+half*128, +128) with tf32 convert
            const float* hp = &g_h[srow * HID_D + kbase + half * 128 + sq];
            float* hs = &Hs[srow * 132 + sq];
#pragma unroll
            for (int j = 0; j < 8; ++j) {
                float4 v = __ldcg((const float4*)(hp + j * 4));
                CVT4(v);
                *(float4*)(hs + j * 4) = v;
            }
            __syncthreads();

            const float* WpH = Wp + half * (16 * 4 * 64);
#pragma unroll
            for (int ks = 0; ks < 16; ++ks) {
                int kk = ks * 8;
                float a[2][4];
#pragma unroll
                for (int mt = 0; mt < 2; ++mt) {
                    const float* ab = &Hs[(m0w + mt * 16 + g) * 132 + kk + t4];
                    a[mt][0] = ab[0];
                    a[mt][2] = ab[4];
                    a[mt][1] = ab[8 * 132];
                    a[mt][3] = ab[8 * 132 + 4];
                }
#pragma unroll
                for (int j = 0; j < 4; ++j) {
                    uint2 bv = *(const uint2*)(WpH + (ks * 4 + j) * 64 + lid * 2);
#pragma unroll
                    for (int mt = 0; mt < 2; ++mt)
                        mma8(c[mt][j], a[mt][0], a[mt][1], a[mt][2], a[mt][3],
                             bv.x, bv.y);
                }
            }
            __syncthreads();
        }

        // write partial gates (.cg, L2-coherent)
        float* P = g_part + (size_t)ksl * (B_SZ * G4);
#pragma unroll
        for (int mt = 0; mt < 2; ++mt) {
#pragma unroll
            for (int j = 0; j < 4; ++j) {
                int row0 = m0w + mt * 16 + g;
                int col  = n0 + n0w + j * 8 + 2 * t4;
                __stcg((float2*)&P[(size_t)row0 * G4 + col],
                       make_float2(c[mt][j].x, c[mt][j].y));
                __stcg((float2*)&P[(size_t)(row0 + 8) * G4 + col],
                       make_float2(c[mt][j].z, c[mt][j].w));
            }
        }

        target += NB;
        grid_bar(target);

        // ---------------- cell phase (2 elements, c in registers) ----------
        {
            float gi0 = x0i + bi, gf0 = x0f + bf, gg0 = x0g + bg, go0 = x0o + bo;
            float gi1 = x1i + bi, gf1 = x1f + bf, gg1 = x1g + bg, go1 = x1o + bo;
#pragma unroll
            for (int s = 0; s < 4; ++s) {
                const float* p0 = g_part + ((size_t)s * B_SZ + b0) * G4 + j0;
                const float* p1 = p0 + (size_t)32 * G4;
                gi0 += __ldcg(p0);        gi1 += __ldcg(p1);
                gf0 += __ldcg(p0 + 1024); gf1 += __ldcg(p1 + 1024);
                gg0 += __ldcg(p0 + 2048); gg1 += __ldcg(p1 + 2048);
                go0 += __ldcg(p0 + 3072); go1 += __ldcg(p1 + 3072);
            }

            float si0 = 1.f / (1.f + expf(-gi0));
            float sf0 = 1.f / (1.f + expf(-gf0));
            float so0 = 1.f / (1.f + expf(-go0));
            c0 = sf0 * c0 + si0 * tanhf(gg0);
            float h0 = so0 * tanhf(c0);

            float si1 = 1.f / (1.f + expf(-gi1));
            float sf1 = 1.f / (1.f + expf(-gf1));
            float so1 = 1.f / (1.f + expf(-go1));
            c1 = sf1 * c1 + si1 * tanhf(gg1);
            float h1 = so1 * tanhf(c1);

            __stcg(&g_h[b0 * HID_D + j0], h0);
            __stcg(&g_h[(b0 + 32) * HID_D + j0], h1);

            if (layer == 0) {
                __stcg(&g_hseq[((size_t)t * B_SZ + b0) * HID_D + j0], h0);
                __stcg(&g_hseq[((size_t)t * B_SZ + b0 + 32) * HID_D + j0], h1);
            } else {
                if (t == L0) out[(size_t)b0 * HID_D + j0] = h0;
                if (t == L1) out[(size_t)(b0 + 32) * HID_D + j0] = h1;
            }
        }

        target += NB;
        grid_bar(target);

        xp0 += xpstep;
        xp1 += xpstep;
    }
}

// ---------------------------------------------------------------------------
// Launcher (11 graph nodes)
// ---------------------------------------------------------------------------
extern "C" void kernel_launch(void* const* d_in, const int* in_sizes, int n_in,
                              void* d_out, int out_size)
{
    const int*   x    = (const int*)d_in[0];
    const int*   len  = (const int*)d_in[1];
    const float* emb  = (const float*)d_in[2];
    const float* Wih0 = (const float*)d_in[3];
    const float* bih0 = (const float*)d_in[4];
    const float* Aih0 = (const float*)d_in[5];
    const float* Bih0 = (const float*)d_in[6];
    const float* Whh0 = (const float*)d_in[7];
    const float* bhh0 = (const float*)d_in[8];
    const float* Ahh0 = (const float*)d_in[9];
    const float* Bhh0 = (const float*)d_in[10];
    const float* Wih1 = (const float*)d_in[11];
    const float* bih1 = (const float*)d_in[12];
    const float* Aih1 = (const float*)d_in[13];
    const float* Bih1 = (const float*)d_in[14];
    const float* Whh1 = (const float*)d_in[15];
    const float* bhh1 = (const float*)d_in[16];
    const float* Ahh1 = (const float*)d_in[17];
    const float* Bhh1 = (const float*)d_in[18];
    float* out = (float*)d_out;

    int n0 = G4 * EMB_D, n1 = G4 * HID_D;
    fold_kernel<<<(n0 + 255) / 256, 256>>>(Wih0, Aih0, Bih0, EMB_D, 0);
    fold_kernel<<<(n1 + 255) / 256, 256>>>(Wih1, Aih1, Bih1, HID_D, 1);
    pack_fold<<<(n1 + 255) / 256, 256>>>(Whh0, Ahh0, Bhh0, 0);
    pack_fold<<<(n1 + 255) / 256, 256>>>(Whh1, Ahh1, Bhh1, 1);

    rowidx_kernel<<<(MROWS + 255) / 256, 256>>>(x);

    dim3 pgrid(G4 / 128, MROWS / 128);   // (32 n-tiles, 256 m-tiles)
    int cellBlocks = (B_SZ * HID_D + 255) / 256;

    // layer 0
    proj_gemm<<<pgrid, 256>>>(emb, bih0, 0);
    initstate_kernel<<<cellBlocks, 256>>>();
    scan_kernel<<<NB, 256>>>(0, bhh0, len, out);

    // layer 1
    proj_gemm<<<pgrid, 256>>>(nullptr, bih1, 1);
    initstate_kernel<<<cellBlocks, 256>>>();
    scan_kernel<<<NB, 256>>>(1, bhh1, len, out);
}